// round 2
// baseline (speedup 1.0000x reference)
#include <cuda_runtime.h>
#include <stdint.h>

#define NHD 12
#define HSD 64
#define HD  768
#define BD  16
#define SD  512
#define BH  (BD*NHD)        /* 192  */
#define MROWS (BD*SD)       /* 8192 */
#define SCALE 0.125f

#define CTX_ELEMS   ((size_t)BD*SD*HD)        /* 6291456  */
#define SCORE_ELEMS ((size_t)BD*NHD*SD*SD)    /* 50331648 */
#define OFF_CTX  ((size_t)0)
#define OFF_ATTN (CTX_ELEMS)
#define OFF_VAL  (OFF_ATTN + SCORE_ELEMS)
#define OFF_QRY  (OFF_VAL  + SCORE_ELEMS)
#define OFF_KEY  (OFF_QRY  + SCORE_ELEMS)

// ---------------- scratch (static __device__, no allocation) ----------------
__device__ float d_Q[MROWS*HD];
__device__ float d_K[MROWS*HD];
__device__ float d_V[MROWS*HD];
__device__ float d_scales[3*HD];
__device__ unsigned long long d_qb[BH*SD];          // sign bits of q along HS
__device__ unsigned long long d_kb[BH*SD];
__device__ unsigned long long d_vt[BH*HSD*8];       // sign bits of v transposed: [bh][d][8 words of k]

// ---------------- 1) per-row weight scales: s_j = mean|W[j,:]| ----------------
// Mimic an XLA-GPU-style row reduce: 32 lanes, stride-32 sequential partials
// (ascending), warp shuffle tree, then IEEE divide by 768.
__global__ void scale_kernel(const float* __restrict__ Wq,
                             const float* __restrict__ Wk,
                             const float* __restrict__ Wv) {
    int row = blockIdx.x;
    int which = blockIdx.y;
    const float* W = (which == 0) ? Wq : (which == 1) ? Wk : Wv;
    int lane = threadIdx.x;
    float s = 0.f;
#pragma unroll
    for (int i = 0; i < 24; i++)
        s += fabsf(W[(size_t)row*HD + lane + 32*i]);
#pragma unroll
    for (int o = 16; o > 0; o >>= 1)
        s += __shfl_down_sync(0xffffffffu, s, o);
    if (lane == 0) d_scales[which*HD + row] = s / 768.0f;
}

// ---------------- 2) projection GEMM: X[8192,768] x qW^T -----------------------
// qW[j,k] = +s_j / -s_j / 0 (exact, matches s*sign(w)), FMA accumulation with a
// single accumulator per output, k strictly ascending, bias added once at end.
// This mirrors the rounding sequence of a cublas/Eigen fp32 GEMM.
__global__ __launch_bounds__(256, 2)
void proj_kernel(const float* __restrict__ X,
                 const float* __restrict__ Wq, const float* __restrict__ Wk,
                 const float* __restrict__ Wv,
                 const float* __restrict__ bq, const float* __restrict__ bk,
                 const float* __restrict__ bv) {
    __shared__ float As[8][128];
    __shared__ float Bs[8][132];

    int tid = threadIdx.x;
    int bn = blockIdx.x;                 // 0..17 (3 matrices x 6 col tiles)
    int m0 = blockIdx.y * 128;
    int which = bn / 6;
    int j0 = (bn % 6) * 128;

    const float* W    = (which == 0) ? Wq : (which == 1) ? Wk : Wv;
    const float* bias = (which == 0) ? bq : (which == 1) ? bk : bv;
    float* dst        = (which == 0) ? d_Q : (which == 1) ? d_K : d_V;

    int tx = tid % 16, ty = tid / 16;
    int lr = tid / 2, lc = (tid % 2) * 4;

    // this thread always loads weight column (j0 + lr): its scale is loop-invariant
    float sj = d_scales[which*HD + j0 + lr];

    float acc[8][8];
#pragma unroll
    for (int i = 0; i < 8; i++)
#pragma unroll
        for (int j = 0; j < 8; j++) acc[i][j] = 0.f;

    for (int kk = 0; kk < HD; kk += 8) {
        float4 av = *(const float4*)&X[(size_t)(m0 + lr)*HD + kk + lc];
        float4 wv = *(const float4*)&W[(size_t)(j0 + lr)*HD + kk + lc];
        As[lc+0][lr] = av.x; As[lc+1][lr] = av.y; As[lc+2][lr] = av.z; As[lc+3][lr] = av.w;
        Bs[lc+0][lr] = (wv.x > 0.f) ? sj : ((wv.x < 0.f) ? -sj : 0.f);
        Bs[lc+1][lr] = (wv.y > 0.f) ? sj : ((wv.y < 0.f) ? -sj : 0.f);
        Bs[lc+2][lr] = (wv.z > 0.f) ? sj : ((wv.z < 0.f) ? -sj : 0.f);
        Bs[lc+3][lr] = (wv.w > 0.f) ? sj : ((wv.w < 0.f) ? -sj : 0.f);
        __syncthreads();
#pragma unroll
        for (int k = 0; k < 8; k++) {
            float4 a0 = *(float4*)&As[k][ty*8];
            float4 a1 = *(float4*)&As[k][ty*8 + 4];
            float4 b0 = *(float4*)&Bs[k][tx*8];
            float4 b1 = *(float4*)&Bs[k][tx*8 + 4];
            float ar[8] = {a0.x,a0.y,a0.z,a0.w,a1.x,a1.y,a1.z,a1.w};
            float br[8] = {b0.x,b0.y,b0.z,b0.w,b1.x,b1.y,b1.z,b1.w};
#pragma unroll
            for (int i = 0; i < 8; i++)
#pragma unroll
                for (int j = 0; j < 8; j++) acc[i][j] = fmaf(ar[i], br[j], acc[i][j]);
        }
        __syncthreads();
    }

    float bb[8];
#pragma unroll
    for (int j = 0; j < 8; j++) bb[j] = bias[j0 + tx*8 + j];
#pragma unroll
    for (int i = 0; i < 8; i++) {
        int m = m0 + ty*8 + i;
        float4 o0, o1;
        o0.x = acc[i][0] + bb[0]; o0.y = acc[i][1] + bb[1];
        o0.z = acc[i][2] + bb[2]; o0.w = acc[i][3] + bb[3];
        o1.x = acc[i][4] + bb[4]; o1.y = acc[i][5] + bb[5];
        o1.z = acc[i][6] + bb[6]; o1.w = acc[i][7] + bb[7];
        *(float4*)&dst[(size_t)m*HD + j0 + tx*8]     = o0;
        *(float4*)&dst[(size_t)m*HD + j0 + tx*8 + 4] = o1;
    }
}

// ---------------- 3) pack sign bits of Q,K along head dim --------------------
__global__ void pack_qk_kernel() {
    int tid = threadIdx.x;
    int warp = tid / 32, lane = tid % 32;
    int idx = blockIdx.x * 8 + warp;                 // 0 .. 2*BH*SD-1
    int tensor = (idx >= BH*SD) ? 1 : 0;
    int r = idx - tensor * (BH*SD);
    int bh = r / SD, s = r % SD;
    int b = bh / NHD, h = bh % NHD;
    const float* src = tensor ? d_K : d_Q;
    size_t base = ((size_t)(b*SD + s))*HD + h*HSD;
    float x0 = src[base + lane];
    float x1 = src[base + 32 + lane];
    unsigned lo = __ballot_sync(0xffffffffu, x0 > 0.f);
    unsigned hi = __ballot_sync(0xffffffffu, x1 > 0.f);
    if (lane == 0) {
        unsigned long long bits = (unsigned long long)lo | ((unsigned long long)hi << 32);
        if (tensor) d_kb[(size_t)bh*SD + s] = bits;
        else        d_qb[(size_t)bh*SD + s] = bits;
    }
}

// ---------------- 4) pack sign bits of V transposed (bits along k/seq) -------
__global__ void pack_vt_kernel() {
    __shared__ float sv[64][68];
    int tid = threadIdx.x;
    int w  = blockIdx.x;        // which 64-seq chunk (0..7)
    int bh = blockIdx.y;
    int b = bh / NHD, h = bh % NHD;
    int row = tid / 4;
    int c0  = (tid % 4) * 16;
    const float* base = d_V + ((size_t)(b*SD + w*64 + row))*HD + h*HSD;
#pragma unroll
    for (int i = 0; i < 4; i++) {
        float4 v = *(const float4*)(base + c0 + 4*i);
        sv[row][c0 + 4*i + 0] = v.x; sv[row][c0 + 4*i + 1] = v.y;
        sv[row][c0 + 4*i + 2] = v.z; sv[row][c0 + 4*i + 3] = v.w;
    }
    __syncthreads();
    int warp = tid / 32, lane = tid % 32;
#pragma unroll
    for (int it = 0; it < 8; it++) {
        int d = warp * 8 + it;
        unsigned lo = __ballot_sync(0xffffffffu, sv[lane][d]      > 0.f);
        unsigned hi = __ballot_sync(0xffffffffu, sv[lane + 32][d] > 0.f);
        if (lane == 0)
            d_vt[((size_t)bh*HSD + d)*8 + w] =
                (unsigned long long)lo | ((unsigned long long)hi << 32);
    }
}

// ---------------- 5) real-valued score GEMMs: C = M M^T * SCALE --------------
// z=0: Q -> query_scores, z=1: K -> key_scores, z=2: V -> value_scores
__global__ __launch_bounds__(256)
void score_kernel(float* __restrict__ out) {
    __shared__ float As[64][68];   // transposed: As[d][row]
    __shared__ float Bs[64][68];
    int bh = blockIdx.y, z = blockIdx.z;
    int qt = blockIdx.x / 8, kt = blockIdx.x % 8;
    int b = bh / NHD, h = bh % NHD;
    const float* src = (z == 0) ? d_Q : (z == 1) ? d_K : d_V;
    size_t off = (z == 0) ? OFF_QRY : (z == 1) ? OFF_KEY : OFF_VAL;

    int tid = threadIdx.x;
    int r = tid / 4, c0 = (tid % 4) * 16;
    const float* abase = src + ((size_t)(b*SD + qt*64 + r))*HD + h*HSD;
    const float* bbase = src + ((size_t)(b*SD + kt*64 + r))*HD + h*HSD;
#pragma unroll
    for (int i = 0; i < 4; i++) {
        float4 va = *(const float4*)(abase + c0 + 4*i);
        As[c0+4*i+0][r] = va.x; As[c0+4*i+1][r] = va.y;
        As[c0+4*i+2][r] = va.z; As[c0+4*i+3][r] = va.w;
        float4 vb = *(const float4*)(bbase + c0 + 4*i);
        Bs[c0+4*i+0][r] = vb.x; Bs[c0+4*i+1][r] = vb.y;
        Bs[c0+4*i+2][r] = vb.z; Bs[c0+4*i+3][r] = vb.w;
    }
    __syncthreads();

    int tx = tid % 16, ty = tid / 16;
    float acc[4][4];
#pragma unroll
    for (int i = 0; i < 4; i++)
#pragma unroll
        for (int j = 0; j < 4; j++) acc[i][j] = 0.f;

#pragma unroll 16
    for (int d = 0; d < 64; d++) {
        float4 a = *(float4*)&As[d][ty*4];
        float4 bvec = *(float4*)&Bs[d][tx*4];
        float ar[4] = {a.x, a.y, a.z, a.w};
        float br[4] = {bvec.x, bvec.y, bvec.z, bvec.w};
#pragma unroll
        for (int i = 0; i < 4; i++)
#pragma unroll
            for (int j = 0; j < 4; j++) acc[i][j] = fmaf(ar[i], br[j], acc[i][j]);
    }

    float* o = out + off + ((size_t)bh*SD + qt*64 + ty*4)*SD + kt*64 + tx*4;
#pragma unroll
    for (int i = 0; i < 4; i++) {
        float4 ov;
        ov.x = acc[i][0]*SCALE; ov.y = acc[i][1]*SCALE;
        ov.z = acc[i][2]*SCALE; ov.w = acc[i][3]*SCALE;
        *(float4*)(o + (size_t)i*SD) = ov;
    }
}

// ---------------- 6) binary attention scores + probs + context ---------------
__global__ __launch_bounds__(256)
void attn_ctx_kernel(const float* __restrict__ mask, float* __restrict__ out) {
    __shared__ unsigned long long skb[512];
    __shared__ unsigned long long svt[512];     // [d][w] -> d*8+w
    __shared__ unsigned long long sqb[64];
    __shared__ unsigned spos[64][16];
    __shared__ unsigned szero[64][16];

    int tid = threadIdx.x;
    int qt = blockIdx.x, bh = blockIdx.y;
    int b = bh / NHD, h = bh % NHD;
    int q0 = qt * 64;

    skb[tid]       = d_kb[(size_t)bh*SD + tid];
    skb[tid + 256] = d_kb[(size_t)bh*SD + tid + 256];
    svt[tid]       = d_vt[(size_t)bh*512 + tid];
    svt[tid + 256] = d_vt[(size_t)bh*512 + tid + 256];
    if (tid < 64) sqb[tid] = d_qb[(size_t)bh*SD + q0 + tid];
    __syncthreads();

    int warp = tid / 32, lane = tid % 32;
    int k1 = warp*32 + lane;
    int k2 = k1 + 256;
    unsigned long long kb1 = skb[k1], kb2 = skb[k2];
    float mk1 = mask[(size_t)b*SD + k1];
    float mk2 = mask[(size_t)b*SD + k2];
    float* attn_base = out + OFF_ATTN + ((size_t)bh*SD + q0)*SD;

    for (int q = 0; q < 64; q++) {
        unsigned long long qw = sqb[q];
        int s1 = 64 - 2*__popcll(qw ^ kb1);
        int s2 = 64 - 2*__popcll(qw ^ kb2);
        float f1 = (float)s1 * SCALE + mk1;
        float f2 = (float)s2 * SCALE + mk2;
        attn_base[(size_t)q*SD + k1] = f1;
        attn_base[(size_t)q*SD + k2] = f2;
        unsigned p1 = __ballot_sync(0xffffffffu, f1 > 0.f);
        unsigned z1 = __ballot_sync(0xffffffffu, f1 == 0.f);
        unsigned p2 = __ballot_sync(0xffffffffu, f2 > 0.f);
        unsigned z2 = __ballot_sync(0xffffffffu, f2 == 0.f);
        if (lane == 0) {
            spos[q][warp]      = p1;  spos[q][warp + 8]  = p2;
            szero[q][warp]     = z1;  szero[q][warp + 8] = z2;
        }
    }
    __syncthreads();

    // context: thread owns (q = tid/4, 16 d's at dg*16)
    int q  = tid / 4;
    int dg = tid % 4;
    float tmp[16];
#pragma unroll
    for (int dd = 0; dd < 16; dd++) {
        int d = dg*16 + dd;
        const unsigned* v32 = (const unsigned*)&svt[d*8];
        int ip = 0, iz = 0;
#pragma unroll
        for (int w16 = 0; w16 < 16; w16++) {
            unsigned V1 = v32[w16];
            unsigned P  = spos[q][w16];
            unsigned Z  = szero[q][w16];
            ip += 2*__popc(P & V1) - __popc(P);
            iz += 2*__popc(Z & V1) - __popc(Z);
        }
        tmp[dd] = (float)ip + 0.5f*(float)iz;
    }
    float* cbase = out + OFF_CTX + ((size_t)(b*SD + q0 + q))*HD + h*HSD + dg*16;
#pragma unroll
    for (int i = 0; i < 4; i++) {
        float4 ov; ov.x = tmp[4*i]; ov.y = tmp[4*i+1]; ov.z = tmp[4*i+2]; ov.w = tmp[4*i+3];
        *(float4*)(cbase + 4*i) = ov;
    }
}

// ------------------------------- launch --------------------------------------
extern "C" void kernel_launch(void* const* d_in, const int* in_sizes, int n_in,
                              void* d_out, int out_size) {
    const float* X    = (const float*)d_in[0];   // hidden_states [16,512,768]
    const float* mask = (const float*)d_in[1];   // attention_mask [16,1,1,512]
    const float* Wq   = (const float*)d_in[2];
    const float* bq   = (const float*)d_in[3];
    const float* Wk   = (const float*)d_in[4];
    const float* bk   = (const float*)d_in[5];
    const float* Wv   = (const float*)d_in[6];
    const float* bv   = (const float*)d_in[7];
    float* out = (float*)d_out;

    scale_kernel<<<dim3(HD, 3), 32>>>(Wq, Wk, Wv);
    proj_kernel<<<dim3(18, 64), 256>>>(X, Wq, Wk, Wv, bq, bk, bv);
    pack_qk_kernel<<<(2*BH*SD)/8, 256>>>();
    pack_vt_kernel<<<dim3(8, BH), 256>>>();
    score_kernel<<<dim3(64, BH, 3), 256>>>(out);
    attn_ctx_kernel<<<dim3(8, BH), 256>>>(mask, out);
}

// round 3
// speedup vs baseline: 1.1089x; 1.1089x over previous
#include <cuda_runtime.h>
#include <stdint.h>

#define NHD 12
#define HSD 64
#define HD  768
#define BD  16
#define SD  512
#define BH  (BD*NHD)        /* 192  */
#define MROWS (BD*SD)       /* 8192 */
#define SCALE 0.125f

#define CTX_ELEMS   ((size_t)BD*SD*HD)        /* 6291456  */
#define SCORE_ELEMS ((size_t)BD*NHD*SD*SD)    /* 50331648 */
#define OFF_CTX  ((size_t)0)
#define OFF_ATTN (CTX_ELEMS)
#define OFF_VAL  (OFF_ATTN + SCORE_ELEMS)
#define OFF_QRY  (OFF_VAL  + SCORE_ELEMS)
#define OFF_KEY  (OFF_QRY  + SCORE_ELEMS)

typedef unsigned long long u64_t;

// ---- packed f32x2 helpers (per-lane IEEE identical to scalar FFMA) ----------
__device__ __forceinline__ u64_t pack2(float lo, float hi) {
    u64_t r; asm("mov.b64 %0, {%1, %2};" : "=l"(r) : "f"(lo), "f"(hi)); return r;
}
__device__ __forceinline__ u64_t bcast2(float x) {
    u64_t r; asm("mov.b64 %0, {%1, %1};" : "=l"(r) : "f"(x)); return r;
}
__device__ __forceinline__ void fma2(u64_t& d, u64_t a, u64_t b) {
    asm("fma.rn.f32x2 %0, %1, %2, %0;" : "+l"(d) : "l"(a), "l"(b));
}
__device__ __forceinline__ u64_t add2(u64_t a, u64_t b) {
    u64_t r; asm("add.rn.f32x2 %0, %1, %2;" : "=l"(r) : "l"(a), "l"(b)); return r;
}
__device__ __forceinline__ u64_t mul2(u64_t a, u64_t b) {
    u64_t r; asm("mul.rn.f32x2 %0, %1, %2;" : "=l"(r) : "l"(a), "l"(b)); return r;
}
__device__ __forceinline__ float2 unpack2(u64_t v) {
    float2 f; asm("mov.b64 {%0, %1}, %2;" : "=f"(f.x), "=f"(f.y) : "l"(v)); return f;
}

// ---------------- scratch (static __device__, no allocation) ----------------
__device__ float d_Q[MROWS*HD];
__device__ float d_K[MROWS*HD];
__device__ float d_V[MROWS*HD];
__device__ float d_scales[3*HD];
__device__ unsigned long long d_qb[BH*SD];          // sign bits of q along HS
__device__ unsigned long long d_kb[BH*SD];
__device__ unsigned long long d_vt[BH*HSD*8];       // sign bits of v transposed

// ---------------- 1) per-row weight scales: s_j = mean|W[j,:]| ----------------
// DO NOT TOUCH: rounding order is correctness-critical (sign bits downstream).
__global__ void scale_kernel(const float* __restrict__ Wq,
                             const float* __restrict__ Wk,
                             const float* __restrict__ Wv) {
    int row = blockIdx.x;
    int which = blockIdx.y;
    const float* W = (which == 0) ? Wq : (which == 1) ? Wk : Wv;
    int lane = threadIdx.x;
    float s = 0.f;
#pragma unroll
    for (int i = 0; i < 24; i++)
        s += fabsf(W[(size_t)row*HD + lane + 32*i]);
#pragma unroll
    for (int o = 16; o > 0; o >>= 1)
        s += __shfl_down_sync(0xffffffffu, s, o);
    if (lane == 0) d_scales[which*HD + row] = s / 768.0f;
}

// ---------------- 2) projection GEMM: X[8192,768] x qW^T ----------------------
// Rounding-critical: one accumulator per output, k strictly ascending, FMA,
// bias added once at end. f32x2 packs two outputs per op (per-lane IEEE).
__global__ __launch_bounds__(256, 2)
void proj_kernel(const float* __restrict__ X,
                 const float* __restrict__ Wq, const float* __restrict__ Wk,
                 const float* __restrict__ Wv,
                 const float* __restrict__ bq, const float* __restrict__ bk,
                 const float* __restrict__ bv) {
    __shared__ float As[16][128];
    __shared__ float Bs[16][132];

    int tid = threadIdx.x;
    int bn = blockIdx.x;                 // 0..17 (3 matrices x 6 col tiles)
    int m0 = blockIdx.y * 128;
    int which = bn / 6;
    int j0 = (bn % 6) * 128;

    const float* W    = (which == 0) ? Wq : (which == 1) ? Wk : Wv;
    const float* bias = (which == 0) ? bq : (which == 1) ? bk : bv;
    float* dst        = (which == 0) ? d_Q : (which == 1) ? d_K : d_V;

    int tx = tid % 16, ty = tid / 16;
    int lr = tid / 2, lc = (tid % 2) * 8;

    float sj = d_scales[which*HD + j0 + lr];

    u64_t acc2[8][4];
#pragma unroll
    for (int i = 0; i < 8; i++)
#pragma unroll
        for (int j = 0; j < 4; j++) acc2[i][j] = 0ull;

    for (int kk = 0; kk < HD; kk += 16) {
        float4 av0 = *(const float4*)&X[(size_t)(m0 + lr)*HD + kk + lc];
        float4 av1 = *(const float4*)&X[(size_t)(m0 + lr)*HD + kk + lc + 4];
        float4 wv0 = *(const float4*)&W[(size_t)(j0 + lr)*HD + kk + lc];
        float4 wv1 = *(const float4*)&W[(size_t)(j0 + lr)*HD + kk + lc + 4];
        As[lc+0][lr] = av0.x; As[lc+1][lr] = av0.y; As[lc+2][lr] = av0.z; As[lc+3][lr] = av0.w;
        As[lc+4][lr] = av1.x; As[lc+5][lr] = av1.y; As[lc+6][lr] = av1.z; As[lc+7][lr] = av1.w;
        Bs[lc+0][lr] = (wv0.x > 0.f) ? sj : ((wv0.x < 0.f) ? -sj : 0.f);
        Bs[lc+1][lr] = (wv0.y > 0.f) ? sj : ((wv0.y < 0.f) ? -sj : 0.f);
        Bs[lc+2][lr] = (wv0.z > 0.f) ? sj : ((wv0.z < 0.f) ? -sj : 0.f);
        Bs[lc+3][lr] = (wv0.w > 0.f) ? sj : ((wv0.w < 0.f) ? -sj : 0.f);
        Bs[lc+4][lr] = (wv1.x > 0.f) ? sj : ((wv1.x < 0.f) ? -sj : 0.f);
        Bs[lc+5][lr] = (wv1.y > 0.f) ? sj : ((wv1.y < 0.f) ? -sj : 0.f);
        Bs[lc+6][lr] = (wv1.z > 0.f) ? sj : ((wv1.z < 0.f) ? -sj : 0.f);
        Bs[lc+7][lr] = (wv1.w > 0.f) ? sj : ((wv1.w < 0.f) ? -sj : 0.f);
        __syncthreads();
#pragma unroll
        for (int k = 0; k < 16; k++) {
            float4 a0 = *(float4*)&As[k][ty*8];
            float4 a1 = *(float4*)&As[k][ty*8 + 4];
            float4 b0 = *(float4*)&Bs[k][tx*8];
            float4 b1 = *(float4*)&Bs[k][tx*8 + 4];
            u64_t bp[4];
            bp[0] = pack2(b0.x, b0.y); bp[1] = pack2(b0.z, b0.w);
            bp[2] = pack2(b1.x, b1.y); bp[3] = pack2(b1.z, b1.w);
            float ar[8] = {a0.x,a0.y,a0.z,a0.w,a1.x,a1.y,a1.z,a1.w};
#pragma unroll
            for (int i = 0; i < 8; i++) {
                u64_t ab = bcast2(ar[i]);
                fma2(acc2[i][0], ab, bp[0]);
                fma2(acc2[i][1], ab, bp[1]);
                fma2(acc2[i][2], ab, bp[2]);
                fma2(acc2[i][3], ab, bp[3]);
            }
        }
        __syncthreads();
    }

    float4 bb0 = *(const float4*)&bias[j0 + tx*8];
    float4 bb1 = *(const float4*)&bias[j0 + tx*8 + 4];
    u64_t bbp[4];
    bbp[0] = pack2(bb0.x, bb0.y); bbp[1] = pack2(bb0.z, bb0.w);
    bbp[2] = pack2(bb1.x, bb1.y); bbp[3] = pack2(bb1.z, bb1.w);
#pragma unroll
    for (int i = 0; i < 8; i++) {
        int m = m0 + ty*8 + i;
        float2 p0 = unpack2(add2(acc2[i][0], bbp[0]));
        float2 p1 = unpack2(add2(acc2[i][1], bbp[1]));
        float2 p2 = unpack2(add2(acc2[i][2], bbp[2]));
        float2 p3 = unpack2(add2(acc2[i][3], bbp[3]));
        float4 o0, o1;
        o0.x = p0.x; o0.y = p0.y; o0.z = p1.x; o0.w = p1.y;
        o1.x = p2.x; o1.y = p2.y; o1.z = p3.x; o1.w = p3.y;
        *(float4*)&dst[(size_t)m*HD + j0 + tx*8]     = o0;
        *(float4*)&dst[(size_t)m*HD + j0 + tx*8 + 4] = o1;
    }
}

// ---------------- 3) pack sign bits of Q,K along head dim --------------------
__global__ void pack_qk_kernel() {
    int tid = threadIdx.x;
    int warp = tid / 32, lane = tid % 32;
    int idx = blockIdx.x * 8 + warp;                 // 0 .. 2*BH*SD-1
    int tensor = (idx >= BH*SD) ? 1 : 0;
    int r = idx - tensor * (BH*SD);
    int bh = r / SD, s = r % SD;
    int b = bh / NHD, h = bh % NHD;
    const float* src = tensor ? d_K : d_Q;
    size_t base = ((size_t)(b*SD + s))*HD + h*HSD;
    float x0 = src[base + lane];
    float x1 = src[base + 32 + lane];
    unsigned lo = __ballot_sync(0xffffffffu, x0 > 0.f);
    unsigned hi = __ballot_sync(0xffffffffu, x1 > 0.f);
    if (lane == 0) {
        unsigned long long bits = (unsigned long long)lo | ((unsigned long long)hi << 32);
        if (tensor) d_kb[(size_t)bh*SD + s] = bits;
        else        d_qb[(size_t)bh*SD + s] = bits;
    }
}

// ---------------- 4) pack sign bits of V transposed (bits along k/seq) -------
__global__ void pack_vt_kernel() {
    __shared__ float sv[64][68];
    int tid = threadIdx.x;
    int w  = blockIdx.x;        // which 64-seq chunk (0..7)
    int bh = blockIdx.y;
    int b = bh / NHD, h = bh % NHD;
    int row = tid / 4;
    int c0  = (tid % 4) * 16;
    const float* base = d_V + ((size_t)(b*SD + w*64 + row))*HD + h*HSD;
#pragma unroll
    for (int i = 0; i < 4; i++) {
        float4 v = *(const float4*)(base + c0 + 4*i);
        sv[row][c0 + 4*i + 0] = v.x; sv[row][c0 + 4*i + 1] = v.y;
        sv[row][c0 + 4*i + 2] = v.z; sv[row][c0 + 4*i + 3] = v.w;
    }
    __syncthreads();
    int warp = tid / 32, lane = tid % 32;
#pragma unroll
    for (int it = 0; it < 8; it++) {
        int d = warp * 8 + it;
        unsigned lo = __ballot_sync(0xffffffffu, sv[lane][d]      > 0.f);
        unsigned hi = __ballot_sync(0xffffffffu, sv[lane + 32][d] > 0.f);
        if (lane == 0)
            d_vt[((size_t)bh*HSD + d)*8 + w] =
                (unsigned long long)lo | ((unsigned long long)hi << 32);
    }
}

// ---------------- 5) real-valued score GEMMs: C = M M^T * SCALE --------------
// 128x128 tiles, 8x8 micro-tile via f32x2. Continuous outputs (1e-3 tolerance).
__global__ __launch_bounds__(256, 2)
void score_kernel(float* __restrict__ out) {
    __shared__ float As[32][132];   // transposed: As[d][row]
    __shared__ float Bs[32][132];
    int bh = blockIdx.y, z = blockIdx.z;
    int qt = blockIdx.x >> 2, kt = blockIdx.x & 3;
    int b = bh / NHD, h = bh % NHD;
    const float* src = (z == 0) ? d_Q : (z == 1) ? d_K : d_V;
    size_t off = (z == 0) ? OFF_QRY : (z == 1) ? OFF_KEY : OFF_VAL;

    int tid = threadIdx.x;
    int row_g = tid / 8, dg = tid % 8;
    int tx = tid % 16, ty = tid / 16;

    u64_t acc2[8][4];
#pragma unroll
    for (int i = 0; i < 8; i++)
#pragma unroll
        for (int j = 0; j < 4; j++) acc2[i][j] = 0ull;

    for (int dc = 0; dc < HSD; dc += 32) {
#pragma unroll
        for (int p = 0; p < 4; p++) {
            int row = p*32 + row_g;
            float4 va = *(const float4*)&src[((size_t)(b*SD + qt*128 + row))*HD + h*HSD + dc + dg*4];
            As[dg*4+0][row] = va.x; As[dg*4+1][row] = va.y;
            As[dg*4+2][row] = va.z; As[dg*4+3][row] = va.w;
            float4 vb = *(const float4*)&src[((size_t)(b*SD + kt*128 + row))*HD + h*HSD + dc + dg*4];
            Bs[dg*4+0][row] = vb.x; Bs[dg*4+1][row] = vb.y;
            Bs[dg*4+2][row] = vb.z; Bs[dg*4+3][row] = vb.w;
        }
        __syncthreads();
#pragma unroll
        for (int d = 0; d < 32; d++) {
            float4 a0 = *(float4*)&As[d][ty*8];
            float4 a1 = *(float4*)&As[d][ty*8 + 4];
            float4 b0 = *(float4*)&Bs[d][tx*8];
            float4 b1 = *(float4*)&Bs[d][tx*8 + 4];
            u64_t bp[4];
            bp[0] = pack2(b0.x, b0.y); bp[1] = pack2(b0.z, b0.w);
            bp[2] = pack2(b1.x, b1.y); bp[3] = pack2(b1.z, b1.w);
            float ar[8] = {a0.x,a0.y,a0.z,a0.w,a1.x,a1.y,a1.z,a1.w};
#pragma unroll
            for (int i = 0; i < 8; i++) {
                u64_t ab = bcast2(ar[i]);
                fma2(acc2[i][0], ab, bp[0]);
                fma2(acc2[i][1], ab, bp[1]);
                fma2(acc2[i][2], ab, bp[2]);
                fma2(acc2[i][3], ab, bp[3]);
            }
        }
        __syncthreads();
    }

    u64_t sc2 = bcast2(SCALE);
    float* o = out + off + ((size_t)bh*SD + qt*128 + ty*8)*SD + kt*128 + tx*8;
#pragma unroll
    for (int i = 0; i < 8; i++) {
        float2 p0 = unpack2(mul2(acc2[i][0], sc2));
        float2 p1 = unpack2(mul2(acc2[i][1], sc2));
        float2 p2 = unpack2(mul2(acc2[i][2], sc2));
        float2 p3 = unpack2(mul2(acc2[i][3], sc2));
        float4 o0, o1;
        o0.x = p0.x; o0.y = p0.y; o0.z = p1.x; o0.w = p1.y;
        o1.x = p2.x; o1.y = p2.y; o1.z = p3.x; o1.w = p3.y;
        *(float4*)(o + (size_t)i*SD)     = o0;
        *(float4*)(o + (size_t)i*SD + 4) = o1;
    }
}

// ---------------- 6) binary attention scores + probs + context ---------------
__global__ __launch_bounds__(256)
void attn_ctx_kernel(const float* __restrict__ mask, float* __restrict__ out) {
    __shared__ unsigned long long skb[512];
    __shared__ unsigned long long svt[512];     // [d][w] -> d*8+w
    __shared__ unsigned long long sqb[64];
    __shared__ unsigned spos[64][16];
    __shared__ unsigned szero[64][16];

    int tid = threadIdx.x;
    int qt = blockIdx.x, bh = blockIdx.y;
    int b = bh / NHD, h = bh % NHD;
    int q0 = qt * 64;

    skb[tid]       = d_kb[(size_t)bh*SD + tid];
    skb[tid + 256] = d_kb[(size_t)bh*SD + tid + 256];
    svt[tid]       = d_vt[(size_t)bh*512 + tid];
    svt[tid + 256] = d_vt[(size_t)bh*512 + tid + 256];
    if (tid < 64) sqb[tid] = d_qb[(size_t)bh*SD + q0 + tid];
    __syncthreads();

    int warp = tid / 32, lane = tid % 32;
    int k1 = warp*32 + lane;
    int k2 = k1 + 256;
    unsigned long long kb1 = skb[k1], kb2 = skb[k2];
    float mk1 = mask[(size_t)b*SD + k1];
    float mk2 = mask[(size_t)b*SD + k2];
    float* attn_base = out + OFF_ATTN + ((size_t)bh*SD + q0)*SD;

    for (int q = 0; q < 64; q++) {
        unsigned long long qw = sqb[q];
        int s1 = 64 - 2*__popcll(qw ^ kb1);
        int s2 = 64 - 2*__popcll(qw ^ kb2);
        float f1 = (float)s1 * SCALE + mk1;
        float f2 = (float)s2 * SCALE + mk2;
        attn_base[(size_t)q*SD + k1] = f1;
        attn_base[(size_t)q*SD + k2] = f2;
        unsigned p1 = __ballot_sync(0xffffffffu, f1 > 0.f);
        unsigned z1 = __ballot_sync(0xffffffffu, f1 == 0.f);
        unsigned p2 = __ballot_sync(0xffffffffu, f2 > 0.f);
        unsigned z2 = __ballot_sync(0xffffffffu, f2 == 0.f);
        if (lane == 0) {
            spos[q][warp]      = p1;  spos[q][warp + 8]  = p2;
            szero[q][warp]     = z1;  szero[q][warp + 8] = z2;
        }
    }
    __syncthreads();

    // context: thread owns (q = tid/4, 16 d's at dg*16)
    int q  = tid / 4;
    int dg = tid % 4;
    float tmp[16];
#pragma unroll
    for (int dd = 0; dd < 16; dd++) {
        int d = dg*16 + dd;
        const unsigned* v32 = (const unsigned*)&svt[d*8];
        int ip = 0, iz = 0;
#pragma unroll
        for (int w16 = 0; w16 < 16; w16++) {
            unsigned V1 = v32[w16];
            unsigned P  = spos[q][w16];
            unsigned Z  = szero[q][w16];
            ip += 2*__popc(P & V1) - __popc(P);
            iz += 2*__popc(Z & V1) - __popc(Z);
        }
        tmp[dd] = (float)ip + 0.5f*(float)iz;
    }
    float* cbase = out + OFF_CTX + ((size_t)(b*SD + q0 + q))*HD + h*HSD + dg*16;
#pragma unroll
    for (int i = 0; i < 4; i++) {
        float4 ov; ov.x = tmp[4*i]; ov.y = tmp[4*i+1]; ov.z = tmp[4*i+2]; ov.w = tmp[4*i+3];
        *(float4*)(cbase + 4*i) = ov;
    }
}

// ------------------------------- launch --------------------------------------
extern "C" void kernel_launch(void* const* d_in, const int* in_sizes, int n_in,
                              void* d_out, int out_size) {
    const float* X    = (const float*)d_in[0];   // hidden_states [16,512,768]
    const float* mask = (const float*)d_in[1];   // attention_mask [16,1,1,512]
    const float* Wq   = (const float*)d_in[2];
    const float* bq   = (const float*)d_in[3];
    const float* Wk   = (const float*)d_in[4];
    const float* bk   = (const float*)d_in[5];
    const float* Wv   = (const float*)d_in[6];
    const float* bv   = (const float*)d_in[7];
    float* out = (float*)d_out;

    scale_kernel<<<dim3(HD, 3), 32>>>(Wq, Wk, Wv);
    proj_kernel<<<dim3(18, 64), 256>>>(X, Wq, Wk, Wv, bq, bk, bv);
    pack_qk_kernel<<<(2*BH*SD)/8, 256>>>();
    pack_vt_kernel<<<dim3(8, BH), 256>>>();
    score_kernel<<<dim3(16, BH, 3), 256>>>(out);
    attn_ctx_kernel<<<dim3(8, BH), 256>>>(mask, out);
}

// round 6
// speedup vs baseline: 1.2672x; 1.1427x over previous
#include <cuda_runtime.h>
#include <cuda_bf16.h>
#include <stdint.h>

#define NHD 12
#define HSD 64
#define HD  768
#define BD  16
#define SD  512
#define BH  (BD*NHD)        /* 192  */
#define MROWS (BD*SD)       /* 8192 */
#define SCALE 0.125f

#define CTX_ELEMS   ((size_t)BD*SD*HD)        /* 6291456  */
#define SCORE_ELEMS ((size_t)BD*NHD*SD*SD)    /* 50331648 */
#define OFF_CTX  ((size_t)0)
#define OFF_ATTN (CTX_ELEMS)
#define OFF_VAL  (OFF_ATTN + SCORE_ELEMS)
#define OFF_QRY  (OFF_VAL  + SCORE_ELEMS)
#define OFF_KEY  (OFF_QRY  + SCORE_ELEMS)

typedef unsigned long long u64_t;

// ---- packed f32x2 helpers (per-lane IEEE identical to scalar FFMA) ----------
__device__ __forceinline__ u64_t pack2(float lo, float hi) {
    u64_t r; asm("mov.b64 %0, {%1, %2};" : "=l"(r) : "f"(lo), "f"(hi)); return r;
}
__device__ __forceinline__ u64_t bcast2(float x) {
    u64_t r; asm("mov.b64 %0, {%1, %1};" : "=l"(r) : "f"(x)); return r;
}
__device__ __forceinline__ void fma2(u64_t& d, u64_t a, u64_t b) {
    asm("fma.rn.f32x2 %0, %1, %2, %0;" : "+l"(d) : "l"(a), "l"(b));
}
__device__ __forceinline__ u64_t add2(u64_t a, u64_t b) {
    u64_t r; asm("add.rn.f32x2 %0, %1, %2;" : "=l"(r) : "l"(a), "l"(b)); return r;
}
__device__ __forceinline__ float2 unpack2(u64_t v) {
    float2 f; asm("mov.b64 {%0, %1}, %2;" : "=f"(f.x), "=f"(f.y) : "l"(v)); return f;
}

// ---- warp-MMA helpers (baseline PTX: works at compute_103) ------------------
__device__ __forceinline__ uint32_t smem_u32(const void* p) {
    uint32_t a;
    asm("{ .reg .u64 t; cvta.to.shared.u64 t, %1; cvt.u32.u64 %0, t; }" : "=r"(a) : "l"(p));
    return a;
}
#define SW128(off) ((off) ^ (((off) >> 3) & 0x70))

__device__ __forceinline__ void ldsm_x4(uint32_t& r0, uint32_t& r1, uint32_t& r2,
                                        uint32_t& r3, uint32_t addr) {
    asm volatile("ldmatrix.sync.aligned.m8n8.x4.shared.b16 {%0,%1,%2,%3}, [%4];"
                 : "=r"(r0), "=r"(r1), "=r"(r2), "=r"(r3) : "r"(addr));
}
__device__ __forceinline__ void mma_16816(float* c, const uint32_t* a, uint32_t b0, uint32_t b1) {
    asm volatile(
        "mma.sync.aligned.m16n8k16.row.col.f32.bf16.bf16.f32 "
        "{%0,%1,%2,%3}, {%4,%5,%6,%7}, {%8,%9}, {%0,%1,%2,%3};"
        : "+f"(c[0]), "+f"(c[1]), "+f"(c[2]), "+f"(c[3])
        : "r"(a[0]), "r"(a[1]), "r"(a[2]), "r"(a[3]), "r"(b0), "r"(b1));
}

// ---------------- scratch (static __device__, no allocation) ----------------
__device__ float d_Q[MROWS*HD];
__device__ float d_K[MROWS*HD];
__device__ float d_V[MROWS*HD];
__device__ float d_scales[3*HD];
__device__ unsigned long long d_qb[BH*SD];
__device__ unsigned long long d_kb[BH*SD];
__device__ unsigned long long d_vt[BH*HSD*8];

// ---------------- 1) per-row weight scales (rounding-critical) ---------------
__global__ void scale_kernel(const float* __restrict__ Wq,
                             const float* __restrict__ Wk,
                             const float* __restrict__ Wv) {
    int row = blockIdx.x;
    int which = blockIdx.y;
    const float* W = (which == 0) ? Wq : (which == 1) ? Wk : Wv;
    int lane = threadIdx.x;
    float s = 0.f;
#pragma unroll
    for (int i = 0; i < 24; i++)
        s += fabsf(W[(size_t)row*HD + lane + 32*i]);
#pragma unroll
    for (int o = 16; o > 0; o >>= 1)
        s += __shfl_down_sync(0xffffffffu, s, o);
    if (lane == 0) d_scales[which*HD + row] = s / 768.0f;
}

// ---------------- 2) projection GEMM (rounding-critical, fp32 FFMA chain) ----
__global__ __launch_bounds__(256, 2)
void proj_kernel(const float* __restrict__ X,
                 const float* __restrict__ Wq, const float* __restrict__ Wk,
                 const float* __restrict__ Wv,
                 const float* __restrict__ bq, const float* __restrict__ bk,
                 const float* __restrict__ bv) {
    __shared__ float As[16][128];
    __shared__ float Bs[16][132];

    int tid = threadIdx.x;
    int bn = blockIdx.x;
    int m0 = blockIdx.y * 128;
    int which = bn / 6;
    int j0 = (bn % 6) * 128;

    const float* W    = (which == 0) ? Wq : (which == 1) ? Wk : Wv;
    const float* bias = (which == 0) ? bq : (which == 1) ? bk : bv;
    float* dst        = (which == 0) ? d_Q : (which == 1) ? d_K : d_V;

    int tx = tid % 16, ty = tid / 16;
    int lr = tid / 2, lc = (tid % 2) * 8;

    float sj = d_scales[which*HD + j0 + lr];

    u64_t acc2[8][4];
#pragma unroll
    for (int i = 0; i < 8; i++)
#pragma unroll
        for (int j = 0; j < 4; j++) acc2[i][j] = 0ull;

    for (int kk = 0; kk < HD; kk += 16) {
        float4 av0 = *(const float4*)&X[(size_t)(m0 + lr)*HD + kk + lc];
        float4 av1 = *(const float4*)&X[(size_t)(m0 + lr)*HD + kk + lc + 4];
        float4 wv0 = *(const float4*)&W[(size_t)(j0 + lr)*HD + kk + lc];
        float4 wv1 = *(const float4*)&W[(size_t)(j0 + lr)*HD + kk + lc + 4];
        As[lc+0][lr] = av0.x; As[lc+1][lr] = av0.y; As[lc+2][lr] = av0.z; As[lc+3][lr] = av0.w;
        As[lc+4][lr] = av1.x; As[lc+5][lr] = av1.y; As[lc+6][lr] = av1.z; As[lc+7][lr] = av1.w;
        Bs[lc+0][lr] = (wv0.x > 0.f) ? sj : ((wv0.x < 0.f) ? -sj : 0.f);
        Bs[lc+1][lr] = (wv0.y > 0.f) ? sj : ((wv0.y < 0.f) ? -sj : 0.f);
        Bs[lc+2][lr] = (wv0.z > 0.f) ? sj : ((wv0.z < 0.f) ? -sj : 0.f);
        Bs[lc+3][lr] = (wv0.w > 0.f) ? sj : ((wv0.w < 0.f) ? -sj : 0.f);
        Bs[lc+4][lr] = (wv1.x > 0.f) ? sj : ((wv1.x < 0.f) ? -sj : 0.f);
        Bs[lc+5][lr] = (wv1.y > 0.f) ? sj : ((wv1.y < 0.f) ? -sj : 0.f);
        Bs[lc+6][lr] = (wv1.z > 0.f) ? sj : ((wv1.z < 0.f) ? -sj : 0.f);
        Bs[lc+7][lr] = (wv1.w > 0.f) ? sj : ((wv1.w < 0.f) ? -sj : 0.f);
        __syncthreads();
#pragma unroll
        for (int k = 0; k < 16; k++) {
            float4 a0 = *(float4*)&As[k][ty*8];
            float4 a1 = *(float4*)&As[k][ty*8 + 4];
            float4 b0 = *(float4*)&Bs[k][tx*8];
            float4 b1 = *(float4*)&Bs[k][tx*8 + 4];
            u64_t bp[4];
            bp[0] = pack2(b0.x, b0.y); bp[1] = pack2(b0.z, b0.w);
            bp[2] = pack2(b1.x, b1.y); bp[3] = pack2(b1.z, b1.w);
            float ar[8] = {a0.x,a0.y,a0.z,a0.w,a1.x,a1.y,a1.z,a1.w};
#pragma unroll
            for (int i = 0; i < 8; i++) {
                u64_t ab = bcast2(ar[i]);
                fma2(acc2[i][0], ab, bp[0]);
                fma2(acc2[i][1], ab, bp[1]);
                fma2(acc2[i][2], ab, bp[2]);
                fma2(acc2[i][3], ab, bp[3]);
            }
        }
        __syncthreads();
    }

    float4 bb0 = *(const float4*)&bias[j0 + tx*8];
    float4 bb1 = *(const float4*)&bias[j0 + tx*8 + 4];
    u64_t bbp[4];
    bbp[0] = pack2(bb0.x, bb0.y); bbp[1] = pack2(bb0.z, bb0.w);
    bbp[2] = pack2(bb1.x, bb1.y); bbp[3] = pack2(bb1.z, bb1.w);
#pragma unroll
    for (int i = 0; i < 8; i++) {
        int m = m0 + ty*8 + i;
        float2 p0 = unpack2(add2(acc2[i][0], bbp[0]));
        float2 p1 = unpack2(add2(acc2[i][1], bbp[1]));
        float2 p2 = unpack2(add2(acc2[i][2], bbp[2]));
        float2 p3 = unpack2(add2(acc2[i][3], bbp[3]));
        float4 o0, o1;
        o0.x = p0.x; o0.y = p0.y; o0.z = p1.x; o0.w = p1.y;
        o1.x = p2.x; o1.y = p2.y; o1.z = p3.x; o1.w = p3.y;
        *(float4*)&dst[(size_t)m*HD + j0 + tx*8]     = o0;
        *(float4*)&dst[(size_t)m*HD + j0 + tx*8 + 4] = o1;
    }
}

// ---------------- 3) pack sign bits of Q,K along head dim --------------------
__global__ void pack_qk_kernel() {
    int tid = threadIdx.x;
    int warp = tid / 32, lane = tid % 32;
    int idx = blockIdx.x * 8 + warp;
    int tensor = (idx >= BH*SD) ? 1 : 0;
    int r = idx - tensor * (BH*SD);
    int bh = r / SD, s = r % SD;
    int b = bh / NHD, h = bh % NHD;
    const float* src = tensor ? d_K : d_Q;
    size_t base = ((size_t)(b*SD + s))*HD + h*HSD;
    float x0 = src[base + lane];
    float x1 = src[base + 32 + lane];
    unsigned lo = __ballot_sync(0xffffffffu, x0 > 0.f);
    unsigned hi = __ballot_sync(0xffffffffu, x1 > 0.f);
    if (lane == 0) {
        unsigned long long bits = (unsigned long long)lo | ((unsigned long long)hi << 32);
        if (tensor) d_kb[(size_t)bh*SD + s] = bits;
        else        d_qb[(size_t)bh*SD + s] = bits;
    }
}

// ---------------- 4) pack sign bits of V transposed --------------------------
__global__ void pack_vt_kernel() {
    __shared__ float sv[64][68];
    int tid = threadIdx.x;
    int w  = blockIdx.x;
    int bh = blockIdx.y;
    int b = bh / NHD, h = bh % NHD;
    int row = tid / 4;
    int c0  = (tid % 4) * 16;
    const float* base = d_V + ((size_t)(b*SD + w*64 + row))*HD + h*HSD;
#pragma unroll
    for (int i = 0; i < 4; i++) {
        float4 v = *(const float4*)(base + c0 + 4*i);
        sv[row][c0 + 4*i + 0] = v.x; sv[row][c0 + 4*i + 1] = v.y;
        sv[row][c0 + 4*i + 2] = v.z; sv[row][c0 + 4*i + 3] = v.w;
    }
    __syncthreads();
    int warp = tid / 32, lane = tid % 32;
#pragma unroll
    for (int it = 0; it < 8; it++) {
        int d = warp * 8 + it;
        unsigned lo = __ballot_sync(0xffffffffu, sv[lane][d]      > 0.f);
        unsigned hi = __ballot_sync(0xffffffffu, sv[lane + 32][d] > 0.f);
        if (lane == 0)
            d_vt[((size_t)bh*HSD + d)*8 + w] =
                (unsigned long long)lo | ((unsigned long long)hi << 32);
    }
}

// ---------------- 5) score GEMMs via warp-MMA (bf16 double split) ------------
// C = M M^T * SCALE; M = hi + lo; C ~= Ah Bh^T + Ah Bl^T + Al Bh^T, fp32 accum.
// 128x128 CTA tile, 32x64 warp tile, ldmatrix + mma.sync.m16n8k16.
#define SM_AH 0
#define SM_AL 16384
#define SM_BH 32768
#define SM_BL 49152
#define SC_SMEM 65536

__global__ __launch_bounds__(256)
void score_mma_kernel(float* __restrict__ out) {
    extern __shared__ char smc[];
    uint32_t sbase = smem_u32(smc);
    int tid = threadIdx.x;
    int wid = tid / 32, lane = tid % 32;

    int bh = blockIdx.y, z = blockIdx.z;
    int qt = blockIdx.x >> 2, kt = blockIdx.x & 3;
    int b = bh / NHD, h = bh % NHD;
    const float* src = (z == 0) ? d_Q : (z == 1) ? d_K : d_V;
    size_t off = (z == 0) ? OFF_QRY : (z == 1) ? OFF_KEY : OFF_VAL;

    // --- convert fp32 -> bf16 hi/lo into swizzled smem (rows = 128B) ---------
    {
        int row = tid >> 1, half = tid & 1;
        const float* arow = src + ((size_t)(b*SD + qt*128 + row))*HD + h*HSD + half*32;
        const float* brow = src + ((size_t)(b*SD + kt*128 + row))*HD + h*HSD + half*32;
        uint32_t rb = (uint32_t)row*128 + half*64;
#pragma unroll
        for (int j = 0; j < 8; j++) {
            uint32_t sw = SW128(rb + j*8);
            float4 x = *(const float4*)(arow + 4*j);
            __nv_bfloat162 h0 = __floats2bfloat162_rn(x.x, x.y);
            __nv_bfloat162 h1 = __floats2bfloat162_rn(x.z, x.w);
            __nv_bfloat162 l0 = __floats2bfloat162_rn(x.x - __bfloat162float(h0.x),
                                                      x.y - __bfloat162float(h0.y));
            __nv_bfloat162 l1 = __floats2bfloat162_rn(x.z - __bfloat162float(h1.x),
                                                      x.w - __bfloat162float(h1.y));
            *(uint2*)(smc + SM_AH + sw) = make_uint2(*(uint32_t*)&h0, *(uint32_t*)&h1);
            *(uint2*)(smc + SM_AL + sw) = make_uint2(*(uint32_t*)&l0, *(uint32_t*)&l1);

            float4 y = *(const float4*)(brow + 4*j);
            h0 = __floats2bfloat162_rn(y.x, y.y);
            h1 = __floats2bfloat162_rn(y.z, y.w);
            l0 = __floats2bfloat162_rn(y.x - __bfloat162float(h0.x),
                                       y.y - __bfloat162float(h0.y));
            l1 = __floats2bfloat162_rn(y.z - __bfloat162float(h1.x),
                                       y.w - __bfloat162float(h1.y));
            *(uint2*)(smc + SM_BH + sw) = make_uint2(*(uint32_t*)&h0, *(uint32_t*)&h1);
            *(uint2*)(smc + SM_BL + sw) = make_uint2(*(uint32_t*)&l0, *(uint32_t*)&l1);
        }
    }
    __syncthreads();

    int wm = wid >> 1, wn = wid & 1;           // 4 x 2 warp grid
    int r8   = (lane & 7) + 8*((lane >> 3) & 1);   // ldmatrix row-within-16
    int cb16 = 16 * (lane >> 4);                   // ldmatrix 16B column select

    float acc[2][8][4];
#pragma unroll
    for (int mg = 0; mg < 2; mg++)
#pragma unroll
        for (int ng = 0; ng < 8; ng++)
#pragma unroll
            for (int c = 0; c < 4; c++) acc[mg][ng][c] = 0.f;

#pragma unroll
    for (int p = 0; p < 3; p++) {
        uint32_t aoff = (p == 2) ? SM_AL : SM_AH;
        uint32_t boff = (p == 1) ? SM_BL : SM_BH;
#pragma unroll
        for (int k0 = 0; k0 < 4; k0++) {
            uint32_t kb = (uint32_t)k0*32 + cb16;
            uint32_t a[2][4];
#pragma unroll
            for (int mg = 0; mg < 2; mg++) {
                uint32_t addr = sbase + aoff +
                    SW128((uint32_t)(wm*32 + mg*16 + r8)*128 + kb);
                ldsm_x4(a[mg][0], a[mg][1], a[mg][2], a[mg][3], addr);
            }
            uint32_t bf[16];
#pragma unroll
            for (int bg = 0; bg < 4; bg++) {
                uint32_t r0, r1, r2, r3;
                uint32_t addr = sbase + boff +
                    SW128((uint32_t)(wn*64 + bg*16 + r8)*128 + kb);
                ldsm_x4(r0, r1, r2, r3, addr);
                bf[4*bg + 0] = r0; bf[4*bg + 1] = r2;   // n-group 2*bg
                bf[4*bg + 2] = r1; bf[4*bg + 3] = r3;   // n-group 2*bg+1
            }
#pragma unroll
            for (int mg = 0; mg < 2; mg++)
#pragma unroll
                for (int ng = 0; ng < 8; ng++)
                    mma_16816(acc[mg][ng], a[mg], bf[2*ng], bf[2*ng + 1]);
        }
    }

    // --- epilogue: write C * SCALE -------------------------------------------
#pragma unroll
    for (int mg = 0; mg < 2; mg++) {
        int row = qt*128 + wm*32 + mg*16 + (lane >> 2);
#pragma unroll
        for (int ng = 0; ng < 8; ng++) {
            int col = kt*128 + wn*64 + ng*8 + 2*(lane & 3);
            float2 v0 = make_float2(acc[mg][ng][0]*SCALE, acc[mg][ng][1]*SCALE);
            float2 v1 = make_float2(acc[mg][ng][2]*SCALE, acc[mg][ng][3]*SCALE);
            *(float2*)&out[off + ((size_t)bh*SD + row    )*SD + col] = v0;
            *(float2*)&out[off + ((size_t)bh*SD + row + 8)*SD + col] = v1;
        }
    }
}

// ---------------- 6) binary attention scores + probs + context ---------------
__global__ __launch_bounds__(256)
void attn_ctx_kernel(const float* __restrict__ mask, float* __restrict__ out) {
    __shared__ unsigned long long skb[512];
    __shared__ unsigned long long svt[512];
    __shared__ unsigned long long sqb[64];
    __shared__ unsigned spos[64][16];
    __shared__ unsigned szero[64][16];

    int tid = threadIdx.x;
    int qt = blockIdx.x, bh = blockIdx.y;
    int b = bh / NHD, h = bh % NHD;
    int q0 = qt * 64;

    skb[tid]       = d_kb[(size_t)bh*SD + tid];
    skb[tid + 256] = d_kb[(size_t)bh*SD + tid + 256];
    svt[tid]       = d_vt[(size_t)bh*512 + tid];
    svt[tid + 256] = d_vt[(size_t)bh*512 + tid + 256];
    if (tid < 64) sqb[tid] = d_qb[(size_t)bh*SD + q0 + tid];
    __syncthreads();

    int warp = tid / 32, lane = tid % 32;
    int k1 = warp*32 + lane;
    int k2 = k1 + 256;
    unsigned long long kb1 = skb[k1], kb2 = skb[k2];
    float mk1 = mask[(size_t)b*SD + k1];
    float mk2 = mask[(size_t)b*SD + k2];
    float* attn_base = out + OFF_ATTN + ((size_t)bh*SD + q0)*SD;

    for (int q = 0; q < 64; q++) {
        unsigned long long qw = sqb[q];
        int s1 = 64 - 2*__popcll(qw ^ kb1);
        int s2 = 64 - 2*__popcll(qw ^ kb2);
        float f1 = (float)s1 * SCALE + mk1;
        float f2 = (float)s2 * SCALE + mk2;
        attn_base[(size_t)q*SD + k1] = f1;
        attn_base[(size_t)q*SD + k2] = f2;
        unsigned p1 = __ballot_sync(0xffffffffu, f1 > 0.f);
        unsigned z1 = __ballot_sync(0xffffffffu, f1 == 0.f);
        unsigned p2 = __ballot_sync(0xffffffffu, f2 > 0.f);
        unsigned z2 = __ballot_sync(0xffffffffu, f2 == 0.f);
        if (lane == 0) {
            spos[q][warp]      = p1;  spos[q][warp + 8]  = p2;
            szero[q][warp]     = z1;  szero[q][warp + 8] = z2;
        }
    }
    __syncthreads();

    int q  = tid / 4;
    int dg = tid % 4;
    float tmp[16];
#pragma unroll
    for (int dd = 0; dd < 16; dd++) {
        int d = dg*16 + dd;
        const unsigned* v32 = (const unsigned*)&svt[d*8];
        int ip = 0, iz = 0;
#pragma unroll
        for (int w16 = 0; w16 < 16; w16++) {
            unsigned V1 = v32[w16];
            unsigned P  = spos[q][w16];
            unsigned Z  = szero[q][w16];
            ip += 2*__popc(P & V1) - __popc(P);
            iz += 2*__popc(Z & V1) - __popc(Z);
        }
        tmp[dd] = (float)ip + 0.5f*(float)iz;
    }
    float* cbase = out + OFF_CTX + ((size_t)(b*SD + q0 + q))*HD + h*HSD + dg*16;
#pragma unroll
    for (int i = 0; i < 4; i++) {
        float4 ov; ov.x = tmp[4*i]; ov.y = tmp[4*i+1]; ov.z = tmp[4*i+2]; ov.w = tmp[4*i+3];
        *(float4*)(cbase + 4*i) = ov;
    }
}

// ------------------------------- launch --------------------------------------
extern "C" void kernel_launch(void* const* d_in, const int* in_sizes, int n_in,
                              void* d_out, int out_size) {
    const float* X    = (const float*)d_in[0];
    const float* mask = (const float*)d_in[1];
    const float* Wq   = (const float*)d_in[2];
    const float* bq   = (const float*)d_in[3];
    const float* Wk   = (const float*)d_in[4];
    const float* bk   = (const float*)d_in[5];
    const float* Wv   = (const float*)d_in[6];
    const float* bv   = (const float*)d_in[7];
    float* out = (float*)d_out;

    static int smem_set = 0;
    if (!smem_set) {
        cudaFuncSetAttribute(score_mma_kernel,
                             cudaFuncAttributeMaxDynamicSharedMemorySize, SC_SMEM);
        smem_set = 1;
    }

    scale_kernel<<<dim3(HD, 3), 32>>>(Wq, Wk, Wv);
    proj_kernel<<<dim3(18, 64), 256>>>(X, Wq, Wk, Wv, bq, bk, bv);
    pack_qk_kernel<<<(2*BH*SD)/8, 256>>>();
    pack_vt_kernel<<<dim3(8, BH), 256>>>();
    score_mma_kernel<<<dim3(16, BH, 3), 256, SC_SMEM>>>(out);
    attn_ctx_kernel<<<dim3(8, BH), 256>>>(mask, out);
}

// round 9
// speedup vs baseline: 1.3656x; 1.0777x over previous
#include <cuda_runtime.h>
#include <cuda_bf16.h>
#include <stdint.h>

#define NHD 12
#define HSD 64
#define HD  768
#define BD  16
#define SD  512
#define BH  (BD*NHD)        /* 192  */
#define MROWS (BD*SD)       /* 8192 */
#define SCALE 0.125f
#define TAU 3e-4f
#define FIX_CAP (1u<<20)

#define CTX_ELEMS   ((size_t)BD*SD*HD)        /* 6291456  */
#define SCORE_ELEMS ((size_t)BD*NHD*SD*SD)    /* 50331648 */
#define OFF_CTX  ((size_t)0)
#define OFF_ATTN (CTX_ELEMS)
#define OFF_VAL  (OFF_ATTN + SCORE_ELEMS)
#define OFF_QRY  (OFF_VAL  + SCORE_ELEMS)
#define OFF_KEY  (OFF_QRY  + SCORE_ELEMS)

// ---- warp-MMA helpers (baseline PTX: works at compute_103) ------------------
__device__ __forceinline__ uint32_t smem_u32(const void* p) {
    uint32_t a;
    asm("{ .reg .u64 t; cvta.to.shared.u64 t, %1; cvt.u32.u64 %0, t; }" : "=r"(a) : "l"(p));
    return a;
}
#define SW128(off) ((off) ^ (((off) >> 3) & 0x70))

__device__ __forceinline__ void ldsm_x4(uint32_t& r0, uint32_t& r1, uint32_t& r2,
                                        uint32_t& r3, uint32_t addr) {
    asm volatile("ldmatrix.sync.aligned.m8n8.x4.shared.b16 {%0,%1,%2,%3}, [%4];"
                 : "=r"(r0), "=r"(r1), "=r"(r2), "=r"(r3) : "r"(addr));
}
__device__ __forceinline__ void mma_16816(float* c, const uint32_t* a, uint32_t b0, uint32_t b1) {
    asm volatile(
        "mma.sync.aligned.m16n8k16.row.col.f32.bf16.bf16.f32 "
        "{%0,%1,%2,%3}, {%4,%5,%6,%7}, {%8,%9}, {%0,%1,%2,%3};"
        : "+f"(c[0]), "+f"(c[1]), "+f"(c[2]), "+f"(c[3])
        : "r"(a[0]), "r"(a[1]), "r"(a[2]), "r"(a[3]), "r"(b0), "r"(b1));
}

// ---------------- scratch (static __device__, no allocation) ----------------
__device__ float d_Q[MROWS*HD];
__device__ float d_K[MROWS*HD];
__device__ float d_V[MROWS*HD];
__device__ float d_scales[3*HD];
__device__ __nv_bfloat16 d_Xh[MROWS*HD];
__device__ __nv_bfloat16 d_Xl[MROWS*HD];
__device__ __nv_bfloat16 d_Wh[3*HD*HD];
__device__ __nv_bfloat16 d_Wl[3*HD*HD];
__device__ unsigned d_fix_cnt;
__device__ unsigned d_fix_idx[FIX_CAP];
__device__ unsigned long long d_qb[BH*SD];
__device__ unsigned long long d_kb[BH*SD];
__device__ unsigned long long d_vt[BH*HSD*8];

// ---------------- 1) per-row weight scales (rounding-critical) ---------------
__global__ void scale_kernel(const float* __restrict__ Wq,
                             const float* __restrict__ Wk,
                             const float* __restrict__ Wv) {
    if (blockIdx.x == 0 && blockIdx.y == 0 && threadIdx.x == 0) d_fix_cnt = 0;
    int row = blockIdx.x;
    int which = blockIdx.y;
    const float* W = (which == 0) ? Wq : (which == 1) ? Wk : Wv;
    int lane = threadIdx.x;
    float s = 0.f;
#pragma unroll
    for (int i = 0; i < 24; i++)
        s += fabsf(W[(size_t)row*HD + lane + 32*i]);
#pragma unroll
    for (int o = 16; o > 0; o >>= 1)
        s += __shfl_down_sync(0xffffffffu, s, o);
    if (lane == 0) d_scales[which*HD + row] = s / 768.0f;
}

// ---------------- 2a) split X into bf16 hi/lo --------------------------------
__global__ void xsplit_kernel(const float* __restrict__ X) {
    size_t i = ((size_t)blockIdx.x * 256 + threadIdx.x) * 4;
    float4 x = *(const float4*)&X[i];
    __nv_bfloat162 h0 = __floats2bfloat162_rn(x.x, x.y);
    __nv_bfloat162 h1 = __floats2bfloat162_rn(x.z, x.w);
    __nv_bfloat162 l0 = __floats2bfloat162_rn(x.x - __bfloat162float(h0.x),
                                              x.y - __bfloat162float(h0.y));
    __nv_bfloat162 l1 = __floats2bfloat162_rn(x.z - __bfloat162float(h1.x),
                                              x.w - __bfloat162float(h1.y));
    *(uint2*)&d_Xh[i] = make_uint2(*(uint32_t*)&h0, *(uint32_t*)&h1);
    *(uint2*)&d_Xl[i] = make_uint2(*(uint32_t*)&l0, *(uint32_t*)&l1);
}

// ---------------- 2b) quantize weights to +-s_j, split into bf16 hi/lo -------
__global__ void wsplit_kernel(const float* __restrict__ Wq,
                              const float* __restrict__ Wk,
                              const float* __restrict__ Wv) {
    int which = blockIdx.y;
    const float* W = (which == 0) ? Wq : (which == 1) ? Wk : Wv;
    size_t i = ((size_t)blockIdx.x * 256 + threadIdx.x) * 4;   // within 768*768
    int row = (int)(i / HD);
    float s = d_scales[which*HD + row];
    __nv_bfloat16 sh = __float2bfloat16_rn(s);
    __nv_bfloat16 sl = __float2bfloat16_rn(s - __bfloat162float(sh));
    float4 w = *(const float4*)&W[i];
    __nv_bfloat16 zero = __float2bfloat16_rn(0.f);
    __nv_bfloat16 h[4], l[4];
    float wf[4] = {w.x, w.y, w.z, w.w};
#pragma unroll
    for (int j = 0; j < 4; j++) {
        if (wf[j] > 0.f)      { h[j] = sh;  l[j] = sl;  }
        else if (wf[j] < 0.f) { h[j] = __hneg(sh); l[j] = __hneg(sl); }
        else                  { h[j] = zero; l[j] = zero; }
    }
    size_t o = (size_t)which*HD*HD + i;
    *(uint2*)&d_Wh[o] = *(uint2*)h;
    *(uint2*)&d_Wl[o] = *(uint2*)l;
}

// ---------------- 2c) projection GEMM via warp-MMA (bf16 double split) -------
// out[m,j] = sum_k X[m,k] * qW[j,k] + bias[j];  approx = XhWh + XhWl + XlWh.
// Elements with |approx| < TAU are recomputed exactly by fix_kernel.
#define PJ_AH 0
#define PJ_AL 16384
#define PJ_BH 32768
#define PJ_BL 49152
#define PJ_SMEM 65536

__global__ __launch_bounds__(256)
void proj_mma_kernel(const float* __restrict__ bq, const float* __restrict__ bk,
                     const float* __restrict__ bv) {
    extern __shared__ char smc[];
    uint32_t sbase = smem_u32(smc);
    int tid = threadIdx.x;
    int wid = tid / 32, lane = tid % 32;

    int bn = blockIdx.x;
    int which = bn / 6;
    int j0 = (bn % 6) * 128;
    int m0 = blockIdx.y * 128;
    const float* bias = (which == 0) ? bq : (which == 1) ? bk : bv;
    float* dst        = (which == 0) ? d_Q : (which == 1) ? d_K : d_V;

    int wm = wid >> 1, wn = wid & 1;
    int r8   = (lane & 7) + 8*((lane >> 3) & 1);
    int cb16 = 16 * (lane >> 4);

    float acc[2][8][4];
#pragma unroll
    for (int mg = 0; mg < 2; mg++)
#pragma unroll
        for (int ng = 0; ng < 8; ng++)
#pragma unroll
            for (int c = 0; c < 4; c++) acc[mg][ng][c] = 0.f;

    int lrow = tid >> 1, lhalf = tid & 1;
    uint32_t rb = (uint32_t)lrow*128 + lhalf*64;

    for (int kt = 0; kt < 12; kt++) {
        int kk = kt * 64;
        const __nv_bfloat16* gAh = d_Xh + (size_t)(m0 + lrow)*HD + kk + lhalf*32;
        const __nv_bfloat16* gAl = d_Xl + (size_t)(m0 + lrow)*HD + kk + lhalf*32;
        const __nv_bfloat16* gBh = d_Wh + ((size_t)which*HD + j0 + lrow)*HD + kk + lhalf*32;
        const __nv_bfloat16* gBl = d_Wl + ((size_t)which*HD + j0 + lrow)*HD + kk + lhalf*32;
        __syncthreads();
#pragma unroll
        for (int j2 = 0; j2 < 4; j2++) {
            uint32_t sw = SW128(rb + j2*16);
            *(uint4*)(smc + PJ_AH + sw) = *(const uint4*)(gAh + j2*8);
            *(uint4*)(smc + PJ_AL + sw) = *(const uint4*)(gAl + j2*8);
            *(uint4*)(smc + PJ_BH + sw) = *(const uint4*)(gBh + j2*8);
            *(uint4*)(smc + PJ_BL + sw) = *(const uint4*)(gBl + j2*8);
        }
        __syncthreads();

#pragma unroll
        for (int p = 0; p < 3; p++) {
            uint32_t aoff = (p == 2) ? PJ_AL : PJ_AH;
            uint32_t boff = (p == 1) ? PJ_BL : PJ_BH;
#pragma unroll
            for (int k0 = 0; k0 < 4; k0++) {
                uint32_t kb = (uint32_t)k0*32 + cb16;
                uint32_t a[2][4];
#pragma unroll
                for (int mg = 0; mg < 2; mg++) {
                    uint32_t addr = sbase + aoff +
                        SW128((uint32_t)(wm*32 + mg*16 + r8)*128 + kb);
                    ldsm_x4(a[mg][0], a[mg][1], a[mg][2], a[mg][3], addr);
                }
                uint32_t bf[16];
#pragma unroll
                for (int bg = 0; bg < 4; bg++) {
                    uint32_t r0, r1, r2, r3;
                    uint32_t addr = sbase + boff +
                        SW128((uint32_t)(wn*64 + bg*16 + r8)*128 + kb);
                    ldsm_x4(r0, r1, r2, r3, addr);
                    bf[4*bg + 0] = r0; bf[4*bg + 1] = r2;
                    bf[4*bg + 2] = r1; bf[4*bg + 3] = r3;
                }
#pragma unroll
                for (int mg = 0; mg < 2; mg++)
#pragma unroll
                    for (int ng = 0; ng < 8; ng++)
                        mma_16816(acc[mg][ng], a[mg], bf[2*ng], bf[2*ng + 1]);
            }
        }
    }

    // epilogue: add bias, write, flag near-zero elements for exact fixup
    unsigned wbase = (unsigned)which * (unsigned)(MROWS*HD);
#pragma unroll
    for (int mg = 0; mg < 2; mg++) {
        int row = m0 + wm*32 + mg*16 + (lane >> 2);
#pragma unroll
        for (int ng = 0; ng < 8; ng++) {
            int col = j0 + wn*64 + ng*8 + 2*(lane & 3);
            float b0 = bias[col], b1 = bias[col+1];
            float v00 = acc[mg][ng][0] + b0, v01 = acc[mg][ng][1] + b1;
            float v10 = acc[mg][ng][2] + b0, v11 = acc[mg][ng][3] + b1;
            *(float2*)&dst[(size_t)row*HD + col]       = make_float2(v00, v01);
            *(float2*)&dst[(size_t)(row + 8)*HD + col] = make_float2(v10, v11);
            if (fabsf(v00) < TAU) { unsigned p = atomicAdd(&d_fix_cnt, 1u); if (p < FIX_CAP) d_fix_idx[p] = wbase + (unsigned)row*HD + col; }
            if (fabsf(v01) < TAU) { unsigned p = atomicAdd(&d_fix_cnt, 1u); if (p < FIX_CAP) d_fix_idx[p] = wbase + (unsigned)row*HD + col + 1; }
            if (fabsf(v10) < TAU) { unsigned p = atomicAdd(&d_fix_cnt, 1u); if (p < FIX_CAP) d_fix_idx[p] = wbase + (unsigned)(row+8)*HD + col; }
            if (fabsf(v11) < TAU) { unsigned p = atomicAdd(&d_fix_cnt, 1u); if (p < FIX_CAP) d_fix_idx[p] = wbase + (unsigned)(row+8)*HD + col + 1; }
        }
    }
}

// ---------------- 2d) exact fixup: serial FMA chain (matches reference) ------
__global__ void fix_kernel(const float* __restrict__ X,
                           const float* __restrict__ Wq, const float* __restrict__ Wk,
                           const float* __restrict__ Wv,
                           const float* __restrict__ bq, const float* __restrict__ bk,
                           const float* __restrict__ bv) {
    unsigned cnt = d_fix_cnt;
    if (cnt > FIX_CAP) cnt = FIX_CAP;
    for (unsigned i = blockIdx.x * blockDim.x + threadIdx.x; i < cnt;
         i += gridDim.x * blockDim.x) {
        unsigned idx = d_fix_idx[i];
        int which = idx / (MROWS*HD);
        unsigned rem = idx - (unsigned)which * (MROWS*HD);
        int m = rem / HD, j = rem % HD;
        const float* W    = (which == 0) ? Wq : (which == 1) ? Wk : Wv;
        const float* bias = (which == 0) ? bq : (which == 1) ? bk : bv;
        float* dst        = (which == 0) ? d_Q : (which == 1) ? d_K : d_V;
        float s = d_scales[which*HD + j];
        const float* xr = X + (size_t)m*HD;
        const float* wr = W + (size_t)j*HD;
        float acc = 0.f;
        for (int k = 0; k < HD; k++) {
            float w = wr[k];
            float b = (w > 0.f) ? s : ((w < 0.f) ? -s : 0.f);
            acc = fmaf(xr[k], b, acc);
        }
        dst[(size_t)m*HD + j] = acc + bias[j];
    }
}

// ---------------- 3) pack sign bits of Q,K along head dim --------------------
__global__ void pack_qk_kernel() {
    int tid = threadIdx.x;
    int warp = tid / 32, lane = tid % 32;
    int idx = blockIdx.x * 8 + warp;
    int tensor = (idx >= BH*SD) ? 1 : 0;
    int r = idx - tensor * (BH*SD);
    int bh = r / SD, s = r % SD;
    int b = bh / NHD, h = bh % NHD;
    const float* src = tensor ? d_K : d_Q;
    size_t base = ((size_t)(b*SD + s))*HD + h*HSD;
    float x0 = src[base + lane];
    float x1 = src[base + 32 + lane];
    unsigned lo = __ballot_sync(0xffffffffu, x0 > 0.f);
    unsigned hi = __ballot_sync(0xffffffffu, x1 > 0.f);
    if (lane == 0) {
        unsigned long long bits = (unsigned long long)lo | ((unsigned long long)hi << 32);
        if (tensor) d_kb[(size_t)bh*SD + s] = bits;
        else        d_qb[(size_t)bh*SD + s] = bits;
    }
}

// ---------------- 4) pack sign bits of V transposed --------------------------
__global__ void pack_vt_kernel() {
    __shared__ float sv[64][68];
    int tid = threadIdx.x;
    int w  = blockIdx.x;
    int bh = blockIdx.y;
    int b = bh / NHD, h = bh % NHD;
    int row = tid / 4;
    int c0  = (tid % 4) * 16;
    const float* base = d_V + ((size_t)(b*SD + w*64 + row))*HD + h*HSD;
#pragma unroll
    for (int i = 0; i < 4; i++) {
        float4 v = *(const float4*)(base + c0 + 4*i);
        sv[row][c0 + 4*i + 0] = v.x; sv[row][c0 + 4*i + 1] = v.y;
        sv[row][c0 + 4*i + 2] = v.z; sv[row][c0 + 4*i + 3] = v.w;
    }
    __syncthreads();
    int warp = tid / 32, lane = tid % 32;
#pragma unroll
    for (int it = 0; it < 8; it++) {
        int d = warp * 8 + it;
        unsigned lo = __ballot_sync(0xffffffffu, sv[lane][d]      > 0.f);
        unsigned hi = __ballot_sync(0xffffffffu, sv[lane + 32][d] > 0.f);
        if (lane == 0)
            d_vt[((size_t)bh*HSD + d)*8 + w] =
                (unsigned long long)lo | ((unsigned long long)hi << 32);
    }
}

// ---------------- 5) score GEMMs via warp-MMA (bf16 double split) ------------
#define SM_AH 0
#define SM_AL 16384
#define SM_BH 32768
#define SM_BL 49152
#define SC_SMEM 65536

__global__ __launch_bounds__(256)
void score_mma_kernel(float* __restrict__ out) {
    extern __shared__ char smc[];
    uint32_t sbase = smem_u32(smc);
    int tid = threadIdx.x;
    int wid = tid / 32, lane = tid % 32;

    int bh = blockIdx.y, z = blockIdx.z;
    int qt = blockIdx.x >> 2, kt = blockIdx.x & 3;
    int b = bh / NHD, h = bh % NHD;
    const float* src = (z == 0) ? d_Q : (z == 1) ? d_K : d_V;
    size_t off = (z == 0) ? OFF_QRY : (z == 1) ? OFF_KEY : OFF_VAL;

    {
        int row = tid >> 1, half = tid & 1;
        const float* arow = src + ((size_t)(b*SD + qt*128 + row))*HD + h*HSD + half*32;
        const float* brow = src + ((size_t)(b*SD + kt*128 + row))*HD + h*HSD + half*32;
        uint32_t rb = (uint32_t)row*128 + half*64;
#pragma unroll
        for (int j = 0; j < 8; j++) {
            uint32_t sw = SW128(rb + j*8);
            float4 x = *(const float4*)(arow + 4*j);
            __nv_bfloat162 h0 = __floats2bfloat162_rn(x.x, x.y);
            __nv_bfloat162 h1 = __floats2bfloat162_rn(x.z, x.w);
            __nv_bfloat162 l0 = __floats2bfloat162_rn(x.x - __bfloat162float(h0.x),
                                                      x.y - __bfloat162float(h0.y));
            __nv_bfloat162 l1 = __floats2bfloat162_rn(x.z - __bfloat162float(h1.x),
                                                      x.w - __bfloat162float(h1.y));
            *(uint2*)(smc + SM_AH + sw) = make_uint2(*(uint32_t*)&h0, *(uint32_t*)&h1);
            *(uint2*)(smc + SM_AL + sw) = make_uint2(*(uint32_t*)&l0, *(uint32_t*)&l1);

            float4 y = *(const float4*)(brow + 4*j);
            h0 = __floats2bfloat162_rn(y.x, y.y);
            h1 = __floats2bfloat162_rn(y.z, y.w);
            l0 = __floats2bfloat162_rn(y.x - __bfloat162float(h0.x),
                                       y.y - __bfloat162float(h0.y));
            l1 = __floats2bfloat162_rn(y.z - __bfloat162float(h1.x),
                                       y.w - __bfloat162float(h1.y));
            *(uint2*)(smc + SM_BH + sw) = make_uint2(*(uint32_t*)&h0, *(uint32_t*)&h1);
            *(uint2*)(smc + SM_BL + sw) = make_uint2(*(uint32_t*)&l0, *(uint32_t*)&l1);
        }
    }
    __syncthreads();

    int wm = wid >> 1, wn = wid & 1;
    int r8   = (lane & 7) + 8*((lane >> 3) & 1);
    int cb16 = 16 * (lane >> 4);

    float acc[2][8][4];
#pragma unroll
    for (int mg = 0; mg < 2; mg++)
#pragma unroll
        for (int ng = 0; ng < 8; ng++)
#pragma unroll
            for (int c = 0; c < 4; c++) acc[mg][ng][c] = 0.f;

#pragma unroll
    for (int p = 0; p < 3; p++) {
        uint32_t aoff = (p == 2) ? SM_AL : SM_AH;
        uint32_t boff = (p == 1) ? SM_BL : SM_BH;
#pragma unroll
        for (int k0 = 0; k0 < 4; k0++) {
            uint32_t kb = (uint32_t)k0*32 + cb16;
            uint32_t a[2][4];
#pragma unroll
            for (int mg = 0; mg < 2; mg++) {
                uint32_t addr = sbase + aoff +
                    SW128((uint32_t)(wm*32 + mg*16 + r8)*128 + kb);
                ldsm_x4(a[mg][0], a[mg][1], a[mg][2], a[mg][3], addr);
            }
            uint32_t bf[16];
#pragma unroll
            for (int bg = 0; bg < 4; bg++) {
                uint32_t r0, r1, r2, r3;
                uint32_t addr = sbase + boff +
                    SW128((uint32_t)(wn*64 + bg*16 + r8)*128 + kb);
                ldsm_x4(r0, r1, r2, r3, addr);
                bf[4*bg + 0] = r0; bf[4*bg + 1] = r2;
                bf[4*bg + 2] = r1; bf[4*bg + 3] = r3;
            }
#pragma unroll
            for (int mg = 0; mg < 2; mg++)
#pragma unroll
                for (int ng = 0; ng < 8; ng++)
                    mma_16816(acc[mg][ng], a[mg], bf[2*ng], bf[2*ng + 1]);
        }
    }

#pragma unroll
    for (int mg = 0; mg < 2; mg++) {
        int row = qt*128 + wm*32 + mg*16 + (lane >> 2);
#pragma unroll
        for (int ng = 0; ng < 8; ng++) {
            int col = kt*128 + wn*64 + ng*8 + 2*(lane & 3);
            float2 v0 = make_float2(acc[mg][ng][0]*SCALE, acc[mg][ng][1]*SCALE);
            float2 v1 = make_float2(acc[mg][ng][2]*SCALE, acc[mg][ng][3]*SCALE);
            *(float2*)&out[off + ((size_t)bh*SD + row    )*SD + col] = v0;
            *(float2*)&out[off + ((size_t)bh*SD + row + 8)*SD + col] = v1;
        }
    }
}

// ---------------- 6) binary attention scores + probs + context ---------------
__global__ __launch_bounds__(256)
void attn_ctx_kernel(const float* __restrict__ mask, float* __restrict__ out) {
    __shared__ unsigned long long skb[512];
    __shared__ unsigned long long svt[512];
    __shared__ unsigned long long sqb[64];
    __shared__ unsigned spos[64][16];
    __shared__ unsigned szero[64][16];

    int tid = threadIdx.x;
    int qt = blockIdx.x, bh = blockIdx.y;
    int b = bh / NHD, h = bh % NHD;
    int q0 = qt * 64;

    skb[tid]       = d_kb[(size_t)bh*SD + tid];
    skb[tid + 256] = d_kb[(size_t)bh*SD + tid + 256];
    svt[tid]       = d_vt[(size_t)bh*512 + tid];
    svt[tid + 256] = d_vt[(size_t)bh*512 + tid + 256];
    if (tid < 64) sqb[tid] = d_qb[(size_t)bh*SD + q0 + tid];
    __syncthreads();

    int warp = tid / 32, lane = tid % 32;
    int k1 = warp*32 + lane;
    int k2 = k1 + 256;
    unsigned long long kb1 = skb[k1], kb2 = skb[k2];
    float mk1 = mask[(size_t)b*SD + k1];
    float mk2 = mask[(size_t)b*SD + k2];
    float* attn_base = out + OFF_ATTN + ((size_t)bh*SD + q0)*SD;

    for (int q = 0; q < 64; q++) {
        unsigned long long qw = sqb[q];
        int s1 = 64 - 2*__popcll(qw ^ kb1);
        int s2 = 64 - 2*__popcll(qw ^ kb2);
        float f1 = (float)s1 * SCALE + mk1;
        float f2 = (float)s2 * SCALE + mk2;
        attn_base[(size_t)q*SD + k1] = f1;
        attn_base[(size_t)q*SD + k2] = f2;
        unsigned p1 = __ballot_sync(0xffffffffu, f1 > 0.f);
        unsigned z1 = __ballot_sync(0xffffffffu, f1 == 0.f);
        unsigned p2 = __ballot_sync(0xffffffffu, f2 > 0.f);
        unsigned z2 = __ballot_sync(0xffffffffu, f2 == 0.f);
        if (lane == 0) {
            spos[q][warp]      = p1;  spos[q][warp + 8]  = p2;
            szero[q][warp]     = z1;  szero[q][warp + 8] = z2;
        }
    }
    __syncthreads();

    int q  = tid / 4;
    int dg = tid % 4;
    float tmp[16];
#pragma unroll
    for (int dd = 0; dd < 16; dd++) {
        int d = dg*16 + dd;
        const unsigned* v32 = (const unsigned*)&svt[d*8];
        int ip = 0, iz = 0;
#pragma unroll
        for (int w16 = 0; w16 < 16; w16++) {
            unsigned V1 = v32[w16];
            unsigned P  = spos[q][w16];
            unsigned Z  = szero[q][w16];
            ip += 2*__popc(P & V1) - __popc(P);
            iz += 2*__popc(Z & V1) - __popc(Z);
        }
        tmp[dd] = (float)ip + 0.5f*(float)iz;
    }
    float* cbase = out + OFF_CTX + ((size_t)(b*SD + q0 + q))*HD + h*HSD + dg*16;
#pragma unroll
    for (int i = 0; i < 4; i++) {
        float4 ov; ov.x = tmp[4*i]; ov.y = tmp[4*i+1]; ov.z = tmp[4*i+2]; ov.w = tmp[4*i+3];
        *(float4*)(cbase + 4*i) = ov;
    }
}

// ------------------------------- launch --------------------------------------
extern "C" void kernel_launch(void* const* d_in, const int* in_sizes, int n_in,
                              void* d_out, int out_size) {
    const float* X    = (const float*)d_in[0];
    const float* mask = (const float*)d_in[1];
    const float* Wq   = (const float*)d_in[2];
    const float* bq   = (const float*)d_in[3];
    const float* Wk   = (const float*)d_in[4];
    const float* bk   = (const float*)d_in[5];
    const float* Wv   = (const float*)d_in[6];
    const float* bv   = (const float*)d_in[7];
    float* out = (float*)d_out;

    static int smem_set = 0;
    if (!smem_set) {
        cudaFuncSetAttribute(score_mma_kernel,
                             cudaFuncAttributeMaxDynamicSharedMemorySize, SC_SMEM);
        cudaFuncSetAttribute(proj_mma_kernel,
                             cudaFuncAttributeMaxDynamicSharedMemorySize, PJ_SMEM);
        smem_set = 1;
    }

    scale_kernel<<<dim3(HD, 3), 32>>>(Wq, Wk, Wv);
    xsplit_kernel<<<(MROWS*HD)/(256*4), 256>>>(X);
    wsplit_kernel<<<dim3((HD*HD)/(256*4), 3), 256>>>(Wq, Wk, Wv);
    proj_mma_kernel<<<dim3(18, 64), 256, PJ_SMEM>>>(bq, bk, bv);
    fix_kernel<<<64, 256>>>(X, Wq, Wk, Wv, bq, bk, bv);
    pack_qk_kernel<<<(2*BH*SD)/8, 256>>>();
    pack_vt_kernel<<<dim3(8, BH), 256>>>();
    score_mma_kernel<<<dim3(16, BH, 3), 256, SC_SMEM>>>(out);
    attn_ctx_kernel<<<dim3(8, BH), 256>>>(mask, out);
}